// round 1
// baseline (speedup 1.0000x reference)
#include <cuda_runtime.h>
#include <math.h>

#define BSZ 4
#define LSEQ 4096
#define DM 256
#define DI 512
#define MTOT (BSZ*LSEQ)        // 16384
#define NCHUNK 64
#define CLEN 64                // NCHUNK*CLEN = LSEQ

// ---------------- scratch (device globals; no allocations allowed) ---------
__device__ float g_xn[MTOT*DM];          // layernormed input (M,256)
__device__ float g_xz[MTOT*2*DI];        // in_proj output (M,1024): [0:512)=xin, [512:1024)=z
__device__ float g_xc[MTOT*DI];          // conv+silu output (M,512)
__device__ float g_dbl[MTOT*48];         // x_proj output (M,48): dt16|B16|C16
__device__ float g_dt[MTOT*DI];          // dt (softplus) -> overwritten with chunk prefix sums
__device__ float g_y[MTOT*DI];           // scan output (local -> final gated)
__device__ float g_xm[MTOT*DM];          // out_proj + skip
__device__ float g_hend[BSZ*NCHUNK*16*DI]; // chunk end states -> chunk incoming states

// ---------------- LayerNorm: x (B,C,L) -> xn (B*L, C) -----------------------
__global__ void ln_kernel(const float* __restrict__ x,
                          const float* __restrict__ nw,
                          const float* __restrict__ nb) {
    __shared__ float s[256*33];
    __shared__ float s_mu[32], s_rs[32];
    int blk = blockIdx.x;            // 512 blocks, 32 l-positions each
    int b  = blk >> 7;
    int l0 = (blk & 127) * 32;
    int tid = threadIdx.x;           // 256
    int lx = tid & 31, cy = tid >> 5;
    const float* xb = x + (size_t)b * DM * LSEQ;
    #pragma unroll 4
    for (int cb = 0; cb < 256; cb += 8) {
        int c = cb + cy;
        s[c*33 + lx] = xb[(size_t)c * LSEQ + l0 + lx];
    }
    __syncthreads();
    if (tid < 32) {
        float sum = 0.f, sq = 0.f;
        #pragma unroll 8
        for (int c = 0; c < 256; c++) { float v = s[c*33 + tid]; sum += v; sq += v*v; }
        float mu = sum * (1.f/256.f);
        float var = sq * (1.f/256.f) - mu*mu;
        s_mu[tid] = mu;
        s_rs[tid] = rsqrtf(var + 1e-5f);
    }
    __syncthreads();
    for (int j = tid; j < 32*256; j += 256) {
        int ll = j >> 8, c = j & 255;
        g_xn[(size_t)(b*LSEQ + l0 + ll)*DM + c] =
            (s[c*33 + ll] - s_mu[ll]) * s_rs[ll] * nw[c] + nb[c];
    }
}

// ---------------- generic 128x128 SGEMM: C = A @ W^T (+ epilogue) ----------
// MODE 0: A=g_xn (K=256)  W=in_proj_w  -> g_xz              (N=1024)
// MODE 1: A=g_y  (K=512)  W=out_proj_w -> g_xm = acc + skip*xT  (N=256)
// MODE 2: A=g_xm (K=256)  W=proj_w     -> out[(b*256+n)*L+l] = acc + bias[n]
template<int MODE, int N, int K>
__global__ __launch_bounds__(256)
void gemm128(const float* __restrict__ W, float* __restrict__ Cout,
             const float* __restrict__ extra, const float* __restrict__ skipPtr) {
    const float* A = (MODE == 0) ? g_xn : (MODE == 1) ? g_y : g_xm;
    __shared__ float As[8][132];
    __shared__ float Bs[8][132];
    int tid = threadIdx.x;
    int m0 = blockIdx.y * 128, n0 = blockIdx.x * 128;
    int ty = tid >> 4, tx = tid & 15;
    float acc[8][8];
    #pragma unroll
    for (int i = 0; i < 8; i++)
        #pragma unroll
        for (int j = 0; j < 8; j++) acc[i][j] = 0.f;

    int lr = tid >> 1, lk = (tid & 1) * 4;
    const float* Ap = A + (size_t)(m0 + lr) * K + lk;
    const float* Wp = W + (size_t)(n0 + lr) * K + lk;

    for (int k0 = 0; k0 < K; k0 += 8) {
        float4 av = *(const float4*)(Ap + k0);
        float4 wv = *(const float4*)(Wp + k0);
        __syncthreads();
        As[lk+0][lr] = av.x; As[lk+1][lr] = av.y; As[lk+2][lr] = av.z; As[lk+3][lr] = av.w;
        Bs[lk+0][lr] = wv.x; Bs[lk+1][lr] = wv.y; Bs[lk+2][lr] = wv.z; Bs[lk+3][lr] = wv.w;
        __syncthreads();
        #pragma unroll
        for (int kk = 0; kk < 8; kk++) {
            float4 a0 = *(const float4*)&As[kk][ty*8];
            float4 a1 = *(const float4*)&As[kk][ty*8+4];
            float4 b0 = *(const float4*)&Bs[kk][tx*8];
            float4 b1 = *(const float4*)&Bs[kk][tx*8+4];
            float a[8] = {a0.x,a0.y,a0.z,a0.w,a1.x,a1.y,a1.z,a1.w};
            float bb[8] = {b0.x,b0.y,b0.z,b0.w,b1.x,b1.y,b1.z,b1.w};
            #pragma unroll
            for (int i = 0; i < 8; i++)
                #pragma unroll
                for (int j = 0; j < 8; j++) acc[i][j] = fmaf(a[i], bb[j], acc[i][j]);
        }
    }

    float skip = 0.f;
    if (MODE == 1) skip = skipPtr[0];
    #pragma unroll
    for (int i = 0; i < 8; i++) {
        int m = m0 + ty*8 + i;
        int bb_ = m >> 12, ll = m & 4095;
        #pragma unroll
        for (int j = 0; j < 8; j++) {
            int n = n0 + tx*8 + j;
            float v = acc[i][j];
            if (MODE == 0) {
                g_xz[(size_t)m * N + n] = v;
            } else if (MODE == 1) {
                g_xm[(size_t)m * 256 + n] = v + skip * extra[(size_t)(bb_*256 + n)*4096 + ll];
            } else {
                Cout[(size_t)(bb_*256 + n)*4096 + ll] = v + extra[n];
            }
        }
    }
}

// ---------------- depthwise causal conv (k=4) + SiLU -----------------------
__global__ void conv_kernel(const float* __restrict__ cw, const float* __restrict__ cb) {
    int m = blockIdx.x;          // 16384
    int d = threadIdx.x;         // 512
    int l = m & 4095;
    float w0 = cw[d*4+0], w1 = cw[d*4+1], w2 = cw[d*4+2], w3 = cw[d*4+3];
    float acc = cb[d];
    if (l >= 3) acc = fmaf(g_xz[(size_t)(m-3)*1024 + d], w0, acc);
    if (l >= 2) acc = fmaf(g_xz[(size_t)(m-2)*1024 + d], w1, acc);
    if (l >= 1) acc = fmaf(g_xz[(size_t)(m-1)*1024 + d], w2, acc);
    acc = fmaf(g_xz[(size_t)m*1024 + d], w3, acc);
    float sg = 1.f / (1.f + __expf(-acc));
    g_xc[(size_t)m*512 + d] = acc * sg;
}

// ---------------- x_proj: dbl = xc @ x_proj_w^T  (N=48, K=512) -------------
__global__ void xproj_kernel(const float* __restrict__ Wp) {
    __shared__ float sw[64*49];
    int tx = threadIdx.x;                     // 64
    int tid = threadIdx.y * 64 + tx;          // 256
    int m = blockIdx.x * 4 + threadIdx.y;
    float acc = 0.f;
    for (int k0 = 0; k0 < 512; k0 += 64) {
        __syncthreads();
        for (int i = tid; i < 48*64; i += 256) {
            int n = i >> 6, k = i & 63;
            sw[k*49 + n] = Wp[(size_t)n*512 + k0 + k];
        }
        __syncthreads();
        if (tx < 48) {
            const float* xr = g_xc + (size_t)m*512 + k0;
            #pragma unroll 8
            for (int k = 0; k < 64; k++) acc = fmaf(xr[k], sw[k*49 + tx], acc);
        }
    }
    if (tx < 48) g_dbl[(size_t)m*48 + tx] = acc;
}

// ---------------- dt = softplus(dt_raw @ dt_proj_w^T + b) ------------------
__global__ void dt_kernel(const float* __restrict__ Wd, const float* __restrict__ bd) {
    __shared__ float sw[16*512];
    __shared__ float sb[512];
    int tid = threadIdx.x;  // 512
    for (int i = tid; i < 8192; i += 512) {
        int d = i >> 4, r = i & 15;
        sw[r*512 + d] = Wd[i];
    }
    sb[tid] = bd[tid];
    __syncthreads();
    int mbase = blockIdx.x * 8;
    for (int mi = 0; mi < 8; mi++) {
        int m = mbase + mi;
        float acc = sb[tid];
        const float* dr = g_dbl + (size_t)m*48;
        #pragma unroll
        for (int r = 0; r < 16; r++) acc = fmaf(dr[r], sw[r*512 + tid], acc);
        g_dt[(size_t)m*512 + tid] = (acc > 20.f) ? acc : log1pf(expf(acc));
    }
}

// ---------------- scan phase 1: per-chunk local recurrence (h0=0) ----------
// also overwrites g_dt with inclusive within-chunk prefix sums of dt,
// stores chunk-end states to g_hend.
__global__ void scan1_kernel(const float* __restrict__ A_log) {
    __shared__ float sbc[2][32];
    int ch = blockIdx.x, b = blockIdx.y, g = blockIdx.z;
    int tid = threadIdx.x;            // 128
    int d = g*128 + tid;
    float a[16], h[16];
    #pragma unroll
    for (int n = 0; n < 16; n++) { a[n] = -expf(A_log[d*16 + n]); h[n] = 0.f; }
    int mbase = b*LSEQ + ch*CLEN;
    if (tid < 32) sbc[0][tid] = g_dbl[(size_t)mbase*48 + 16 + tid];
    float S = 0.f;
    for (int i = 0; i < CLEN; i++) {
        __syncthreads();
        if (i < CLEN-1 && tid < 32)
            sbc[(i+1)&1][tid] = g_dbl[(size_t)(mbase+i+1)*48 + 16 + tid];
        int m = mbase + i;
        float u   = g_xc[(size_t)m*512 + d];
        float dtv = g_dt[(size_t)m*512 + d];
        S += dtv;
        g_dt[(size_t)m*512 + d] = S;
        float du = dtv * u;
        const float* sB = sbc[i&1];
        const float* sC = sbc[i&1] + 16;
        float y = 0.f;
        #pragma unroll
        for (int n = 0; n < 16; n++) {
            float dA = __expf(dtv * a[n]);
            h[n] = fmaf(h[n], dA, du * sB[n]);
            y = fmaf(h[n], sC[n], y);
        }
        g_y[(size_t)m*512 + d] = y;
    }
    size_t base = (size_t)((b*NCHUNK + ch)*16) * 512 + d;
    #pragma unroll
    for (int n = 0; n < 16; n++) g_hend[base + (size_t)n*512] = h[n];
}

// ---------------- scan phase 2: propagate states across chunks -------------
// g_hend[chunk] (end state with h0=0) -> incoming state for chunk (in place)
__global__ void scan2_kernel(const float* __restrict__ A_log) {
    int n = blockIdx.x, b = blockIdx.y, d = threadIdx.x;  // 16 x 4, 512
    float an = -expf(A_log[d*16 + n]);
    float hprev = 0.f;
    for (int ch = 0; ch < NCHUNK; ch++) {
        float Send = g_dt[(size_t)(b*LSEQ + ch*CLEN + CLEN-1)*512 + d];
        size_t idx = (size_t)((b*NCHUNK + ch)*16 + n)*512 + d;
        float tmp = g_hend[idx];
        g_hend[idx] = hprev;
        hprev = fmaf(__expf(an * Send), hprev, tmp);
    }
}

// ---------------- scan phase 3: fix-up + D skip + z gating ------------------
__global__ void scan3_kernel(const float* __restrict__ A_log,
                             const float* __restrict__ Dp) {
    __shared__ float sc[2][16];
    int ch = blockIdx.x, b = blockIdx.y, g = blockIdx.z;
    int tid = threadIdx.x;            // 128
    int d = g*128 + tid;
    float a[16], hin[16];
    size_t hbase = (size_t)((b*NCHUNK + ch)*16) * 512 + d;
    #pragma unroll
    for (int n = 0; n < 16; n++) {
        a[n]   = -expf(A_log[d*16 + n]);
        hin[n] = g_hend[hbase + (size_t)n*512];
    }
    float Dd = Dp[d];
    int mbase = b*LSEQ + ch*CLEN;
    if (tid < 16) sc[0][tid] = g_dbl[(size_t)mbase*48 + 32 + tid];
    for (int i = 0; i < CLEN; i++) {
        __syncthreads();
        if (i < CLEN-1 && tid < 16)
            sc[(i+1)&1][tid] = g_dbl[(size_t)(mbase+i+1)*48 + 32 + tid];
        int m = mbase + i;
        float S  = g_dt[(size_t)m*512 + d];
        float u  = g_xc[(size_t)m*512 + d];
        float z  = g_xz[(size_t)m*1024 + 512 + d];
        float yl = g_y[(size_t)m*512 + d];
        const float* C = sc[i&1];
        float yf = 0.f;
        #pragma unroll
        for (int n = 0; n < 16; n++)
            yf = fmaf(C[n] * __expf(a[n]*S), hin[n], yf);
        float y = yl + yf + u*Dd;
        y *= z / (1.f + __expf(-z));   // * silu(z)
        g_y[(size_t)m*512 + d] = y;
    }
}

// ---------------------------------------------------------------------------
extern "C" void kernel_launch(void* const* d_in, const int* in_sizes, int n_in,
                              void* d_out, int out_size) {
    const float* x         = (const float*)d_in[0];
    const float* norm_w    = (const float*)d_in[1];
    const float* norm_b    = (const float*)d_in[2];
    const float* in_proj_w = (const float*)d_in[3];
    const float* conv_w    = (const float*)d_in[4];
    const float* conv_b    = (const float*)d_in[5];
    const float* x_proj_w  = (const float*)d_in[6];
    const float* dt_proj_w = (const float*)d_in[7];
    const float* dt_proj_b = (const float*)d_in[8];
    const float* A_log     = (const float*)d_in[9];
    const float* D_ssm     = (const float*)d_in[10];
    const float* out_proj_w= (const float*)d_in[11];
    const float* proj_w    = (const float*)d_in[12];
    const float* proj_b    = (const float*)d_in[13];
    const float* skip      = (const float*)d_in[14];
    float* out = (float*)d_out;

    ln_kernel<<<512, 256>>>(x, norm_w, norm_b);
    gemm128<0,1024,256><<<dim3(8,128), 256>>>(in_proj_w, nullptr, nullptr, nullptr);
    conv_kernel<<<MTOT, 512>>>(conv_w, conv_b);
    xproj_kernel<<<4096, dim3(64,4)>>>(x_proj_w);
    dt_kernel<<<2048, 512>>>(dt_proj_w, dt_proj_b);
    scan1_kernel<<<dim3(NCHUNK,BSZ,4), 128>>>(A_log);
    scan2_kernel<<<dim3(16,BSZ), 512>>>(A_log);
    scan3_kernel<<<dim3(NCHUNK,BSZ,4), 128>>>(A_log, D_ssm);
    gemm128<1,256,512><<<dim3(2,128), 256>>>(out_proj_w, nullptr, x, skip);
    gemm128<2,256,256><<<dim3(2,128), 256>>>(proj_w, out, proj_b, nullptr);
}

// round 2
// speedup vs baseline: 1.2686x; 1.2686x over previous
#include <cuda_runtime.h>
#include <math.h>

#define BSZ 4
#define LSEQ 4096
#define DM 256
#define DI 512
#define MTOT (BSZ*LSEQ)        // 16384
#define NCHUNK 64
#define CLEN 64                // NCHUNK*CLEN = LSEQ

// ---------------- scratch (device globals; no allocations allowed) ---------
__device__ float g_xn[MTOT*DM];          // layernormed input (M,256)
__device__ float g_xz[MTOT*2*DI];        // in_proj output (M,1024): [0:512)=xin, [512:1024)=z
__device__ float g_xc[MTOT*DI];          // conv+silu output (M,512)
__device__ float g_dbl[MTOT*48];         // x_proj output (M,48): dt16|B16|C16
__device__ float g_dt[MTOT*DI];          // dt (softplus) -> overwritten with chunk prefix sums
__device__ float g_y[MTOT*DI];           // scan output (local -> final gated)
__device__ float g_xm[MTOT*DM];          // out_proj + skip
__device__ float g_hend[BSZ*NCHUNK*16*DI]; // chunk end states -> chunk incoming states

// ---------------- LayerNorm: x (B,C,L) -> xn (B*L, C) -----------------------
__global__ void ln_kernel(const float* __restrict__ x,
                          const float* __restrict__ nw,
                          const float* __restrict__ nb) {
    __shared__ float s[256*33];
    __shared__ float ps[8][33], pq[8][33];
    __shared__ float s_mu[32], s_rs[32];
    int blk = blockIdx.x;            // 512 blocks, 32 l-positions each
    int b  = blk >> 7;
    int l0 = (blk & 127) * 32;
    int tid = threadIdx.x;           // 256
    int lx = tid & 31, cy = tid >> 5;
    const float* xb = x + (size_t)b * DM * LSEQ;
    #pragma unroll 4
    for (int cb = 0; cb < 256; cb += 8) {
        int c = cb + cy;
        s[c*33 + lx] = xb[(size_t)c * LSEQ + l0 + lx];
    }
    __syncthreads();
    // parallel partial reduction: 8 channel-groups x 32 l-positions
    {
        float sum = 0.f, sq = 0.f;
        int c0 = cy * 32;
        #pragma unroll 8
        for (int c = c0; c < c0 + 32; c++) { float v = s[c*33 + lx]; sum += v; sq += v*v; }
        ps[cy][lx] = sum; pq[cy][lx] = sq;
    }
    __syncthreads();
    if (tid < 32) {
        float sum = 0.f, sq = 0.f;
        #pragma unroll
        for (int p = 0; p < 8; p++) { sum += ps[p][tid]; sq += pq[p][tid]; }
        float mu = sum * (1.f/256.f);
        float var = sq * (1.f/256.f) - mu*mu;
        s_mu[tid] = mu;
        s_rs[tid] = rsqrtf(var + 1e-5f);
    }
    __syncthreads();
    for (int j = tid; j < 32*256; j += 256) {
        int ll = j >> 8, c = j & 255;
        g_xn[(size_t)(b*LSEQ + l0 + ll)*DM + c] =
            (s[c*33 + ll] - s_mu[ll]) * s_rs[ll] * nw[c] + nb[c];
    }
}

// ---------------- generic 128x128 SGEMM: C = A @ W^T (+ epilogue) ----------
// KT=16 k-tile, double-buffered global->register prefetch.
// MODE 0: A=g_xn (K=256)  W=in_proj_w  -> g_xz              (N=1024)
// MODE 1: A=g_y  (K=512)  W=out_proj_w -> g_xm = acc + skip*xT  (N=256)
// MODE 2: A=g_xm (K=256)  W=proj_w     -> out[(b*256+n)*L+l] = acc + bias[n]
template<int MODE, int N, int K>
__global__ __launch_bounds__(256)
void gemm128(const float* __restrict__ W, float* __restrict__ Cout,
             const float* __restrict__ extra, const float* __restrict__ skipPtr) {
    const float* A = (MODE == 0) ? g_xn : (MODE == 1) ? g_y : g_xm;
    __shared__ float As[16][132];
    __shared__ float Bs[16][132];
    int tid = threadIdx.x;
    int m0 = blockIdx.y * 128, n0 = blockIdx.x * 128;
    int ty = tid >> 4, tx = tid & 15;
    float acc[8][8];
    #pragma unroll
    for (int i = 0; i < 8; i++)
        #pragma unroll
        for (int j = 0; j < 8; j++) acc[i][j] = 0.f;

    int lr = tid >> 1, lk = (tid & 1) * 4;   // each thread loads k=[lk..lk+3] and [lk+8..lk+11]
    const float* Ap = A + (size_t)(m0 + lr) * K + lk;
    const float* Wp = W + (size_t)(n0 + lr) * K + lk;

    float4 a0v = *(const float4*)(Ap);
    float4 a1v = *(const float4*)(Ap + 8);
    float4 w0v = *(const float4*)(Wp);
    float4 w1v = *(const float4*)(Wp + 8);

    for (int k0 = 0; k0 < K; k0 += 16) {
        As[lk+0][lr] = a0v.x; As[lk+1][lr] = a0v.y; As[lk+2][lr] = a0v.z; As[lk+3][lr] = a0v.w;
        As[lk+8][lr] = a1v.x; As[lk+9][lr] = a1v.y; As[lk+10][lr] = a1v.z; As[lk+11][lr] = a1v.w;
        Bs[lk+0][lr] = w0v.x; Bs[lk+1][lr] = w0v.y; Bs[lk+2][lr] = w0v.z; Bs[lk+3][lr] = w0v.w;
        Bs[lk+8][lr] = w1v.x; Bs[lk+9][lr] = w1v.y; Bs[lk+10][lr] = w1v.z; Bs[lk+11][lr] = w1v.w;
        __syncthreads();
        if (k0 + 16 < K) {
            a0v = *(const float4*)(Ap + k0 + 16);
            a1v = *(const float4*)(Ap + k0 + 24);
            w0v = *(const float4*)(Wp + k0 + 16);
            w1v = *(const float4*)(Wp + k0 + 24);
        }
        #pragma unroll
        for (int kk = 0; kk < 16; kk++) {
            float4 fa0 = *(const float4*)&As[kk][ty*8];
            float4 fa1 = *(const float4*)&As[kk][ty*8+4];
            float4 fb0 = *(const float4*)&Bs[kk][tx*8];
            float4 fb1 = *(const float4*)&Bs[kk][tx*8+4];
            float a[8] = {fa0.x,fa0.y,fa0.z,fa0.w,fa1.x,fa1.y,fa1.z,fa1.w};
            float bb[8] = {fb0.x,fb0.y,fb0.z,fb0.w,fb1.x,fb1.y,fb1.z,fb1.w};
            #pragma unroll
            for (int i = 0; i < 8; i++)
                #pragma unroll
                for (int j = 0; j < 8; j++) acc[i][j] = fmaf(a[i], bb[j], acc[i][j]);
        }
        __syncthreads();
    }

    float skip = 0.f;
    if (MODE == 1) skip = skipPtr[0];
    #pragma unroll
    for (int i = 0; i < 8; i++) {
        int m = m0 + ty*8 + i;
        int bb_ = m >> 12, ll = m & 4095;
        #pragma unroll
        for (int j = 0; j < 8; j++) {
            int n = n0 + tx*8 + j;
            float v = acc[i][j];
            if (MODE == 0) {
                g_xz[(size_t)m * N + n] = v;
            } else if (MODE == 1) {
                g_xm[(size_t)m * 256 + n] = v + skip * extra[(size_t)(bb_*256 + n)*4096 + ll];
            } else {
                Cout[(size_t)(bb_*256 + n)*4096 + ll] = v + extra[n];
            }
        }
    }
}

// ---------------- depthwise causal conv (k=4) + SiLU, 8 rows/block ---------
__global__ void conv_kernel(const float* __restrict__ cw, const float* __restrict__ cb) {
    int d = threadIdx.x;          // 512
    int m0 = blockIdx.x * 8;      // 2048 blocks
    int l0 = m0 & 4095;
    float w0 = cw[d*4+0], w1 = cw[d*4+1], w2 = cw[d*4+2], w3 = cw[d*4+3];
    float bias = cb[d];
    float r[11];
    #pragma unroll
    for (int i = 0; i < 11; i++) {
        int off = i - 3;
        r[i] = (l0 + off >= 0) ? g_xz[(size_t)(m0 + off)*1024 + d] : 0.f;
    }
    #pragma unroll
    for (int j = 0; j < 8; j++) {
        float acc = bias;
        acc = fmaf(r[j],   w0, acc);
        acc = fmaf(r[j+1], w1, acc);
        acc = fmaf(r[j+2], w2, acc);
        acc = fmaf(r[j+3], w3, acc);
        float sg = 1.f / (1.f + __expf(-acc));
        g_xc[(size_t)(m0+j)*512 + d] = acc * sg;
    }
}

// ---------------- x_proj: dbl = xc @ x_proj_w^T  (M=16384, N=48, K=512) ----
// 128 threads, M-tile 64. Thread = 2 rows x 12 n. Transposed A-smem.
__global__ __launch_bounds__(128)
void xproj_kernel(const float* __restrict__ Wp) {
    __shared__ float As[64][66];   // [k][row]
    __shared__ float Ws[64][52];   // [k][n] (padded)
    int tid = threadIdx.x;              // 128
    int m0 = blockIdx.x * 64;           // 256 blocks
    int row0 = (tid >> 2) * 2;          // 0..62 even
    int ng   = (tid & 3) * 12;          // 0,12,24,36
    float acc0[12], acc1[12];
    #pragma unroll
    for (int j = 0; j < 12; j++) { acc0[j] = 0.f; acc1[j] = 0.f; }

    for (int k0 = 0; k0 < 512; k0 += 64) {
        __syncthreads();
        // A tile: 64 rows x 64 k, transposed store. 1024 float4 / 128 thr = 8 each.
        #pragma unroll
        for (int jj = 0; jj < 8; jj++) {
            int idx = tid + jj*128;
            int r = idx >> 4, kq = (idx & 15) * 4;
            float4 v = *(const float4*)&g_xc[(size_t)(m0+r)*512 + k0 + kq];
            As[kq+0][r] = v.x; As[kq+1][r] = v.y; As[kq+2][r] = v.z; As[kq+3][r] = v.w;
        }
        // W tile: 48 n x 64 k -> Ws[k][n]. 3072 scalars / 128 = 24 each.
        #pragma unroll
        for (int jj = 0; jj < 24; jj++) {
            int i = tid + jj*128;
            int k = i & 63, n = i >> 6;
            Ws[k][n] = Wp[(size_t)n*512 + k0 + k];
        }
        __syncthreads();
        #pragma unroll 16
        for (int k = 0; k < 64; k++) {
            float2 a = *(const float2*)&As[k][row0];
            float4 wA = *(const float4*)&Ws[k][ng];
            float4 wB = *(const float4*)&Ws[k][ng+4];
            float4 wC = *(const float4*)&Ws[k][ng+8];
            float w[12] = {wA.x,wA.y,wA.z,wA.w, wB.x,wB.y,wB.z,wB.w, wC.x,wC.y,wC.z,wC.w};
            #pragma unroll
            for (int j = 0; j < 12; j++) {
                acc0[j] = fmaf(a.x, w[j], acc0[j]);
                acc1[j] = fmaf(a.y, w[j], acc1[j]);
            }
        }
    }
    #pragma unroll
    for (int j = 0; j < 12; j++) {
        g_dbl[(size_t)(m0+row0  )*48 + ng + j] = acc0[j];
        g_dbl[(size_t)(m0+row0+1)*48 + ng + j] = acc1[j];
    }
}

// ---------------- dt = softplus(dt_raw @ dt_proj_w^T + b) ------------------
__global__ void dt_kernel(const float* __restrict__ Wd, const float* __restrict__ bd) {
    __shared__ float sw[16*512];
    __shared__ float sb[512];
    int tid = threadIdx.x;  // 512
    for (int i = tid; i < 8192; i += 512) {
        int d = i >> 4, r = i & 15;
        sw[r*512 + d] = Wd[i];
    }
    sb[tid] = bd[tid];
    __syncthreads();
    int mbase = blockIdx.x * 8;
    for (int mi = 0; mi < 8; mi++) {
        int m = mbase + mi;
        float acc = sb[tid];
        const float* dr = g_dbl + (size_t)m*48;
        #pragma unroll
        for (int r = 0; r < 16; r++) acc = fmaf(dr[r], sw[r*512 + tid], acc);
        g_dt[(size_t)m*512 + tid] = (acc > 20.f) ? acc : __logf(1.f + __expf(acc));
    }
}

// ---------------- scan phase 1: per-chunk local recurrence (h0=0) ----------
__global__ void scan1_kernel(const float* __restrict__ A_log) {
    __shared__ float sbc[2][32];
    int ch = blockIdx.x, b = blockIdx.y, g = blockIdx.z;
    int tid = threadIdx.x;            // 128
    int d = g*128 + tid;
    float a[16], h[16];
    #pragma unroll
    for (int n = 0; n < 16; n++) { a[n] = -expf(A_log[d*16 + n]); h[n] = 0.f; }
    int mbase = b*LSEQ + ch*CLEN;
    if (tid < 32) sbc[0][tid] = g_dbl[(size_t)mbase*48 + 16 + tid];
    float S = 0.f;
    float u   = g_xc[(size_t)mbase*512 + d];
    float dtv = g_dt[(size_t)mbase*512 + d];
    for (int i = 0; i < CLEN; i++) {
        __syncthreads();
        float u_n = 0.f, dt_n = 0.f;
        if (i < CLEN-1) {
            if (tid < 32) sbc[(i+1)&1][tid] = g_dbl[(size_t)(mbase+i+1)*48 + 16 + tid];
            u_n  = g_xc[(size_t)(mbase+i+1)*512 + d];
            dt_n = g_dt[(size_t)(mbase+i+1)*512 + d];
        }
        int m = mbase + i;
        S += dtv;
        g_dt[(size_t)m*512 + d] = S;
        float du = dtv * u;
        const float* sB = sbc[i&1];
        const float* sC = sbc[i&1] + 16;
        float y = 0.f;
        #pragma unroll
        for (int n = 0; n < 16; n++) {
            float dA = __expf(dtv * a[n]);
            h[n] = fmaf(h[n], dA, du * sB[n]);
            y = fmaf(h[n], sC[n], y);
        }
        g_y[(size_t)m*512 + d] = y;
        u = u_n; dtv = dt_n;
    }
    size_t base = (size_t)((b*NCHUNK + ch)*16) * 512 + d;
    #pragma unroll
    for (int n = 0; n < 16; n++) g_hend[base + (size_t)n*512] = h[n];
}

// ---------------- scan phase 2: propagate states across chunks -------------
__global__ void scan2_kernel(const float* __restrict__ A_log) {
    int n = blockIdx.x, b = blockIdx.y, d = threadIdx.x;  // 16 x 4, 512
    float an = -expf(A_log[d*16 + n]);
    float hprev = 0.f;
    for (int ch = 0; ch < NCHUNK; ch++) {
        float Send = g_dt[(size_t)(b*LSEQ + ch*CLEN + CLEN-1)*512 + d];
        size_t idx = (size_t)((b*NCHUNK + ch)*16 + n)*512 + d;
        float tmp = g_hend[idx];
        g_hend[idx] = hprev;
        hprev = fmaf(__expf(an * Send), hprev, tmp);
    }
}

// ---------------- scan phase 3: fix-up + D skip + z gating ------------------
__global__ void scan3_kernel(const float* __restrict__ A_log,
                             const float* __restrict__ Dp) {
    __shared__ float sc[2][16];
    int ch = blockIdx.x, b = blockIdx.y, g = blockIdx.z;
    int tid = threadIdx.x;            // 128
    int d = g*128 + tid;
    float a[16], hin[16];
    size_t hbase = (size_t)((b*NCHUNK + ch)*16) * 512 + d;
    #pragma unroll
    for (int n = 0; n < 16; n++) {
        a[n]   = -expf(A_log[d*16 + n]);
        hin[n] = g_hend[hbase + (size_t)n*512];
    }
    float Dd = Dp[d];
    int mbase = b*LSEQ + ch*CLEN;
    if (tid < 16) sc[0][tid] = g_dbl[(size_t)mbase*48 + 32 + tid];
    float S  = g_dt[(size_t)mbase*512 + d];
    float u  = g_xc[(size_t)mbase*512 + d];
    float z  = g_xz[(size_t)mbase*1024 + 512 + d];
    float yl = g_y[(size_t)mbase*512 + d];
    for (int i = 0; i < CLEN; i++) {
        __syncthreads();
        float S_n=0.f, u_n=0.f, z_n=0.f, yl_n=0.f;
        if (i < CLEN-1) {
            if (tid < 16) sc[(i+1)&1][tid] = g_dbl[(size_t)(mbase+i+1)*48 + 32 + tid];
            S_n  = g_dt[(size_t)(mbase+i+1)*512 + d];
            u_n  = g_xc[(size_t)(mbase+i+1)*512 + d];
            z_n  = g_xz[(size_t)(mbase+i+1)*1024 + 512 + d];
            yl_n = g_y[(size_t)(mbase+i+1)*512 + d];
        }
        int m = mbase + i;
        const float* C = sc[i&1];
        float yf = 0.f;
        #pragma unroll
        for (int n = 0; n < 16; n++)
            yf = fmaf(C[n] * __expf(a[n]*S), hin[n], yf);
        float y = yl + yf + u*Dd;
        y *= z / (1.f + __expf(-z));   // * silu(z)
        g_y[(size_t)m*512 + d] = y;
        S = S_n; u = u_n; z = z_n; yl = yl_n;
    }
}

// ---------------------------------------------------------------------------
extern "C" void kernel_launch(void* const* d_in, const int* in_sizes, int n_in,
                              void* d_out, int out_size) {
    const float* x         = (const float*)d_in[0];
    const float* norm_w    = (const float*)d_in[1];
    const float* norm_b    = (const float*)d_in[2];
    const float* in_proj_w = (const float*)d_in[3];
    const float* conv_w    = (const float*)d_in[4];
    const float* conv_b    = (const float*)d_in[5];
    const float* x_proj_w  = (const float*)d_in[6];
    const float* dt_proj_w = (const float*)d_in[7];
    const float* dt_proj_b = (const float*)d_in[8];
    const float* A_log     = (const float*)d_in[9];
    const float* D_ssm     = (const float*)d_in[10];
    const float* out_proj_w= (const float*)d_in[11];
    const float* proj_w    = (const float*)d_in[12];
    const float* proj_b    = (const float*)d_in[13];
    const float* skip      = (const float*)d_in[14];
    float* out = (float*)d_out;

    ln_kernel<<<512, 256>>>(x, norm_w, norm_b);
    gemm128<0,1024,256><<<dim3(8,128), 256>>>(in_proj_w, nullptr, nullptr, nullptr);
    conv_kernel<<<2048, 512>>>(conv_w, conv_b);
    xproj_kernel<<<256, 128>>>(x_proj_w);
    dt_kernel<<<2048, 512>>>(dt_proj_w, dt_proj_b);
    scan1_kernel<<<dim3(NCHUNK,BSZ,4), 128>>>(A_log);
    scan2_kernel<<<dim3(16,BSZ), 512>>>(A_log);
    scan3_kernel<<<dim3(NCHUNK,BSZ,4), 128>>>(A_log, D_ssm);
    gemm128<1,256,512><<<dim3(2,128), 256>>>(out_proj_w, nullptr, x, skip);
    gemm128<2,256,256><<<dim3(2,128), 256>>>(proj_w, out, proj_b, nullptr);
}